// round 16
// baseline (speedup 1.0000x reference)
#include <cuda_runtime.h>
#include <cuda_fp16.h>
#include <cstdint>

// Problem constants
#define B_  32
#define N_  4096
#define E_  8192
#define D_  128
#define ROWS_TOTAL (B_*N_)        // 131072
#define NEDGE (B_*E_)             // 262144

// ---------------- device-global scratch ------------------------------------------
__device__ __half g_agg[B_*N_*D_];     // 32MB fp16 aggregation buffer
__device__ __half g_wt[2*384*128];     // transposed fp16 weights: [mat][col(384)][k(128)]

// ---------------- smem layout (bytes), 64-row CTA, 2 CTAs/SM ---------------------
// A + single-gate B tiles: 272B rows (128 halves + pad).   No XOR anywhere.
// merged B tiles: 256 rows x 144B (64 halves + pad), strip-reordered.
#define OFF_BIAS  0                 // 768 floats (3072)
#define OFF_AG    3072              // agg  64x272  (17408)
#define OFF_AH    20480             // h    64x272  (17408)
#define OFF_B0    37888             // ring buf 0 (36864: merged 256x144 / single 128x272)
#define OFF_B1    74752             // ring buf 1 (36864)
#define SMEM_TOTAL 111616           // x2 = 223232

__device__ __forceinline__ uint32_t smem_u32(const void* p) {
    uint32_t a;
    asm("{ .reg .u64 t; cvta.to.shared.u64 t, %1; cvt.u32.u64 %0, t; }" : "=r"(a) : "l"(p));
    return a;
}
__device__ __forceinline__ void ldsm4(uint32_t d[4], uint32_t addr) {
    asm volatile("ldmatrix.sync.aligned.m8n8.x4.shared.b16 {%0,%1,%2,%3}, [%4];"
                 : "=r"(d[0]), "=r"(d[1]), "=r"(d[2]), "=r"(d[3]) : "r"(addr));
}
__device__ __forceinline__ void mma_16816(float c[4], const uint32_t a[4], uint32_t b0, uint32_t b1) {
    asm volatile(
        "mma.sync.aligned.m16n8k16.row.col.f32.f16.f16.f32 "
        "{%0,%1,%2,%3}, {%4,%5,%6,%7}, {%8,%9}, {%0,%1,%2,%3};"
        : "+f"(c[0]), "+f"(c[1]), "+f"(c[2]), "+f"(c[3])
        : "r"(a[0]), "r"(a[1]), "r"(a[2]), "r"(a[3]), "r"(b0), "r"(b1));
}
__device__ __forceinline__ float tanh_ap(float x) {
    float y; asm("tanh.approx.f32 %0, %1;" : "=f"(y) : "f"(x)); return y;
}
__device__ __forceinline__ float sigf(float x) { return fmaf(0.5f, tanh_ap(0.5f * x), 0.5f); }

#define CP_ASYNC16(dst, src) \
    asm volatile("cp.async.cg.shared.global [%0], [%1], 16;" :: "r"(dst), "l"(src) : "memory")
#define CP_COMMIT() asm volatile("cp.async.commit_group;" ::: "memory")
#define CP_WAIT(n)  asm volatile("cp.async.wait_group %0;" :: "n"(n) : "memory")

// ================================================================================
// Kernel 1: fused weight transpose/convert (blocks 0..383) + agg zero (rest)
// ================================================================================
__global__ void prep_zero_kernel(const float* __restrict__ kern, const float* __restrict__ rker) {
    if (blockIdx.x < 384) {
        int i = blockIdx.x * 256 + threadIdx.x;     // 0..98303
        int mat = i / (384 * 128);
        int rem = i - mat * (384 * 128);
        int col = rem >> 7;
        int k   = rem & 127;
        const float* W = mat ? rker : kern;
        g_wt[i] = __float2half_rn(W[k * 384 + col]);
    } else {
        const uint4 z = make_uint4(0u, 0u, 0u, 0u);
        int n16 = (B_ * N_ * D_ * 2) / 16;
        int stride = (gridDim.x - 384) * 256;
        for (int i = (blockIdx.x - 384) * 256 + threadIdx.x; i < n16; i += stride)
            reinterpret_cast<uint4*>(g_agg)[i] = z;
    }
}

// ================================================================================
// Kernel 2: scatter-add into fp16 g_agg (2 edges/warp, v4.f16x2 REDG)
// ================================================================================
__global__ void scatter_kernel(const float* __restrict__ msgs, const int* __restrict__ conn) {
    int gwarp = (blockIdx.x * blockDim.x + threadIdx.x) >> 5;
    int lane  = threadIdx.x & 31;
    int edge  = gwarp * 2 + (lane >> 4);
    if (edge >= NEDGE) return;
    int sub = lane & 15;
    int b   = edge >> 13;
    int tgt;
    if (sub == 0) tgt = conn[edge * 2 + 1];
    tgt = __shfl_sync(0xffffffffu, tgt, lane & 16);
    const float4* mp = reinterpret_cast<const float4*>(msgs) + (size_t)edge * 32 + sub * 2;
    float4 m0 = mp[0];
    float4 m1 = mp[1];
    union { __half2 h; uint32_t u; } p0, p1, p2, p3;
    p0.h = __floats2half2_rn(m0.x, m0.y);
    p1.h = __floats2half2_rn(m0.z, m0.w);
    p2.h = __floats2half2_rn(m1.x, m1.y);
    p3.h = __floats2half2_rn(m1.z, m1.w);
    __half* dst = g_agg + ((size_t)((b << 12) + tgt)) * 128 + sub * 8;
    asm volatile("red.global.add.noftz.v4.f16x2 [%0], {%1, %2, %3, %4};"
                 :: "l"(dst), "r"(p0.u), "r"(p1.u), "r"(p2.u), "r"(p3.u) : "memory");
}

// ================================================================================
// Kernel 3: fused dual-GEMM + GRU epilogue.
// 2048 CTAs x 64 rows, 256 threads (8 warps, 2x4 grid).
// Merged z|r phases (warp tile 32x64, strip-reordered B), padded rows, no XOR.
// ================================================================================

// merged half-k B tile: 256 src cols -> strip-reordered rows, 144B stride.
// dst row p(n) = ((n>>5)&3)*64 + (n>>7)*32 + (n&31); kh = k-half of source.
__device__ __forceinline__ void pref_merged(uint32_t dst, const __half* srcbase, int kh, int tid) {
    const char* s = reinterpret_cast<const char*>(srcbase) + kh * 128;
    for (int c = tid; c < 2048; c += 256) {
        int n  = c >> 3, c8 = c & 7;
        int p  = ((n >> 5) & 3) * 64 + (n >> 7) * 32 + (n & 31);
        CP_ASYNC16(dst + (uint32_t)(p * 144 + c8 * 16), s + (size_t)n * 256 + c8 * 16);
    }
    CP_COMMIT();
}
// full-k single-gate B tile: 128 rows x 256B data, 272B stride
__device__ __forceinline__ void pref_full(uint32_t dst, const __half* src, int tid) {
    const char* s = reinterpret_cast<const char*>(src);
    for (int c = tid; c < 2048; c += 256) {
        int row = c >> 4, c16 = c & 15;
        CP_ASYNC16(dst + (uint32_t)(row * 272 + c16 * 16), s + (size_t)c * 16);
    }
    CP_COMMIT();
}
// A tile (agg): 64 rows x 256B data, 272B stride
__device__ __forceinline__ void pref_ag(uint32_t dst, const __half* src, int tid) {
    const char* s = reinterpret_cast<const char*>(src);
    for (int c = tid; c < 1024; c += 256) {
        int row = c >> 4, c16 = c & 15;
        CP_ASYNC16(dst + (uint32_t)(row * 272 + c16 * 16), s + (size_t)c * 16);
    }
    CP_COMMIT();
}

// merged half-k GEMM: acc[2][8] += A(32 x k64) @ B(64 rows x k64)^T.  KB = 2*S.
#define GEMM_M(KB, AROW, BROW) do { \
    _Pragma("unroll") \
    for (int kcp = 0; kcp < 2; kcp++) { \
        const uint32_t aoffk = (uint32_t)(((KB) + kcp) * 64); \
        const uint32_t boffk = (uint32_t)(kcp * 64); \
        uint32_t A0[2][4], A1[2][4]; \
        _Pragma("unroll") \
        for (int mt = 0; mt < 2; mt++) { \
            ldsm4(A0[mt], (AROW) + mt * 4352 + aoffk); \
            ldsm4(A1[mt], (AROW) + mt * 4352 + aoffk + 32); \
        } \
        _Pragma("unroll") \
        for (int nt = 0; nt < 8; nt++) { \
            uint32_t Bf[4]; \
            ldsm4(Bf, (BROW) + nt * 1152 + boffk); \
            _Pragma("unroll") \
            for (int mt = 0; mt < 2; mt++) { \
                mma_16816(acc[mt][nt], A0[mt], Bf[0], Bf[1]); \
                mma_16816(acc[mt][nt], A1[mt], Bf[2], Bf[3]); \
            } \
        } \
    } } while (0)

// single-gate full-k GEMM: acc[2][0..3] += A(32x128) @ B(128x32)^T  (272B rows)
#define GEMM_S(AROW, BBASE) do { \
    _Pragma("unroll") \
    for (int kc = 0; kc < 4; kc++) { \
        uint32_t A0[2][4], A1[2][4]; \
        _Pragma("unroll") \
        for (int mt = 0; mt < 2; mt++) { \
            ldsm4(A0[mt], (AROW) + mt * 4352 + kc * 64); \
            ldsm4(A1[mt], (AROW) + mt * 4352 + kc * 64 + 32); \
        } \
        _Pragma("unroll") \
        for (int nt = 0; nt < 4; nt++) { \
            uint32_t Bf[4]; \
            ldsm4(Bf, (BBASE) + nt * 2176 + kc * 64); \
            _Pragma("unroll") \
            for (int mt = 0; mt < 2; mt++) { \
                mma_16816(acc[mt][nt], A0[mt], Bf[0], Bf[1]); \
                mma_16816(acc[mt][nt], A1[mt], Bf[2], Bf[3]); \
            } \
        } \
    } } while (0)

__global__ void __launch_bounds__(256, 2)
gru_gemm_kernel(const float* __restrict__ atom_state,
                const float* __restrict__ bias,
                float* __restrict__ out)
{
    extern __shared__ char smem[];
    const uint32_t sb = smem_u32(smem);
    const int tid  = threadIdx.x;
    const int wid  = tid >> 5;
    const int lane = tid & 31;
    const int wr   = wid & 1;          // row group (2 x 32 rows)
    const int wc   = wid >> 1;         // col group (4 x 32 cols per gate)
    const int g4   = lane >> 2;
    const int tig  = lane & 3;
    const int t    = lane >> 3;
    const int r8   = lane & 7;
    const int row0 = blockIdx.x * 64;

    float* bias_s = reinterpret_cast<float*>(smem + OFF_BIAS);

    // ---- prolog: g1{B0=Wx_zr k0}, g2{AG}, g3{B1=Wx_zr k1}; bias; h staged ----
    pref_merged(sb + OFF_B0, g_wt, 0, tid);
    pref_ag(sb + OFF_AG, g_agg + (size_t)row0 * 128, tid);
    pref_merged(sb + OFF_B1, g_wt, 1, tid);

    {
        const float4* hp = reinterpret_cast<const float4*>(atom_state + (size_t)row0 * 128);
        float4 hv[8];
#pragma unroll
        for (int k = 0; k < 8; k++) hv[k] = hp[tid + k * 256];
        for (int i = tid; i < 768; i += 256) bias_s[i] = bias[i];
#pragma unroll
        for (int k = 0; k < 8; k++) {
            int idx = tid + k * 256;
            int row = idx >> 5, f4 = idx & 31;
            union { __half2 h2[2]; uint2 u; } cv;
            cv.h2[0] = __floats2half2_rn(hv[k].x, hv[k].y);
            cv.h2[1] = __floats2half2_rn(hv[k].z, hv[k].w);
            *reinterpret_cast<uint2*>(smem + OFF_AH + row * 272 + f4 * 8) = cv.u;
        }
    }

    // per-lane ldsm bases (all further offsets are immediates)
    const uint32_t aoff = (uint32_t)((wr * 32 + (t & 1) * 8 + r8) * 272 + (t >> 1) * 16);
    const uint32_t agRow = sb + OFF_AG + aoff;
    const uint32_t ahRow = sb + OFF_AH + aoff;
    const uint32_t bm0 = sb + OFF_B0 + (uint32_t)((wc * 64 + r8) * 144 + t * 16);  // merged
    const uint32_t bm1 = sb + OFF_B1 + (uint32_t)((wc * 64 + r8) * 144 + t * 16);
    const uint32_t bs0 = sb + OFF_B0 + (uint32_t)((wc * 32 + r8) * 272 + t * 16);  // single
    const uint32_t bs1 = sb + OFF_B1 + (uint32_t)((wc * 32 + r8) * 272 + t * 16);

    float acc[2][8][4];
    __half2 zpk[2][4][2];
    __half2 rpk[2][4][2];

#pragma unroll
    for (int mt = 0; mt < 2; mt++)
#pragma unroll
        for (int nt = 0; nt < 8; nt++)
            acc[mt][nt][0] = acc[mt][nt][1] = acc[mt][nt][2] = acc[mt][nt][3] = 0.f;

    // ===== stage 0: agg @ Wx_zr (k0) =====
    CP_WAIT(1);                       // B0 + AG done (B1 pending); AH via sync
    __syncthreads();
    GEMM_M(0, agRow, bm0);
    __syncthreads();
    pref_merged(sb + OFF_B0, g_wt + 384 * 128, 0, tid);   // Wh_zr k0

    // ===== stage 1: agg @ Wx_zr (k1) =====
    CP_WAIT(1);
    __syncthreads();
    GEMM_M(2, agRow, bm1);
    __syncthreads();
    pref_merged(sb + OFF_B1, g_wt + 384 * 128, 1, tid);   // Wh_zr k1

    // ===== stage 2: + h @ Wh_zr (k0) =====
    CP_WAIT(1);
    __syncthreads();
    GEMM_M(0, ahRow, bm0);
    __syncthreads();
    pref_full(sb + OFF_B0, g_wt + (size_t)(384 + 256) * 128, tid);   // Wh_h

    // ===== stage 3: + h @ Wh_zr (k1) =====
    CP_WAIT(1);
    __syncthreads();
    GEMM_M(2, ahRow, bm1);
    __syncthreads();
    pref_full(sb + OFF_B1, g_wt + (size_t)256 * 128, tid);           // Wx_h

    // ===== sigma epilogue: z (nt 0..3), r (nt 4..7); warp's own 32 cols =====
#pragma unroll
    for (int mt = 0; mt < 2; mt++)
#pragma unroll
        for (int nt = 0; nt < 4; nt++) {
            int col = wc * 32 + nt * 8 + tig * 2;
            float zb0 = bias_s[col]     + bias_s[384 + col];
            float zb1 = bias_s[col + 1] + bias_s[384 + col + 1];
            zpk[mt][nt][0] = __floats2half2_rn(sigf(acc[mt][nt][0] + zb0), sigf(acc[mt][nt][1] + zb1));
            zpk[mt][nt][1] = __floats2half2_rn(sigf(acc[mt][nt][2] + zb0), sigf(acc[mt][nt][3] + zb1));
            float rb0 = bias_s[128 + col]     + bias_s[384 + 128 + col];
            float rb1 = bias_s[128 + col + 1] + bias_s[384 + 128 + col + 1];
            rpk[mt][nt][0] = __floats2half2_rn(sigf(acc[mt][nt + 4][0] + rb0), sigf(acc[mt][nt + 4][1] + rb1));
            rpk[mt][nt][1] = __floats2half2_rn(sigf(acc[mt][nt + 4][2] + rb0), sigf(acc[mt][nt + 4][3] + rb1));
        }

    // ===== stage 4: acc = h @ Wh_h ; rpk *= (acc + bh) =====
    CP_WAIT(1);
    __syncthreads();
#pragma unroll
    for (int mt = 0; mt < 2; mt++)
#pragma unroll
        for (int nt = 0; nt < 4; nt++)
            acc[mt][nt][0] = acc[mt][nt][1] = acc[mt][nt][2] = acc[mt][nt][3] = 0.f;
    GEMM_S(ahRow, bs0);
#pragma unroll
    for (int mt = 0; mt < 2; mt++)
#pragma unroll
        for (int nt = 0; nt < 4; nt++) {
            int col = wc * 32 + nt * 8 + tig * 2;
            float b0 = bias_s[384 + 256 + col];
            float b1 = bias_s[384 + 256 + col + 1];
            float2 rA = __half22float2(rpk[mt][nt][0]);
            float2 rB = __half22float2(rpk[mt][nt][1]);
            rpk[mt][nt][0] = __floats2half2_rn(rA.x * (acc[mt][nt][0] + b0), rA.y * (acc[mt][nt][1] + b1));
            rpk[mt][nt][1] = __floats2half2_rn(rB.x * (acc[mt][nt][2] + b0), rB.y * (acc[mt][nt][3] + b1));
        }

    // ===== stage 5: acc = agg @ Wx_h ; final epilogue =====
    CP_WAIT(0);
    __syncthreads();
#pragma unroll
    for (int mt = 0; mt < 2; mt++)
#pragma unroll
        for (int nt = 0; nt < 4; nt++)
            acc[mt][nt][0] = acc[mt][nt][1] = acc[mt][nt][2] = acc[mt][nt][3] = 0.f;
    GEMM_S(agRow, bs1);

#pragma unroll
    for (int mt = 0; mt < 2; mt++) {
        const int rowA = wr * 32 + mt * 16 + g4;
        const int rowB = rowA + 8;
#pragma unroll
        for (int nt = 0; nt < 4; nt++) {
            int col = wc * 32 + nt * 8 + tig * 2;
            float b0 = bias_s[256 + col];
            float b1 = bias_s[256 + col + 1];
            float2 tA = __half22float2(rpk[mt][nt][0]);
            float2 tB = __half22float2(rpk[mt][nt][1]);
            float2 zA = __half22float2(zpk[mt][nt][0]);
            float2 zB = __half22float2(zpk[mt][nt][1]);
            float2 hA = __half22float2(*reinterpret_cast<const __half2*>(
                smem + OFF_AH + rowA * 272 + col * 2));
            float2 hB = __half22float2(*reinterpret_cast<const __half2*>(
                smem + OFF_AH + rowB * 272 + col * 2));

            float hh0 = tanh_ap(acc[mt][nt][0] + b0 + tA.x);
            float hh1 = tanh_ap(acc[mt][nt][1] + b1 + tA.y);
            float hh2 = tanh_ap(acc[mt][nt][2] + b0 + tB.x);
            float hh3 = tanh_ap(acc[mt][nt][3] + b1 + tB.y);

            float2 oA = make_float2(zA.x * hA.x + (1.f - zA.x) * hh0,
                                    zA.y * hA.y + (1.f - zA.y) * hh1);
            float2 oB = make_float2(zB.x * hB.x + (1.f - zB.x) * hh2,
                                    zB.y * hB.y + (1.f - zB.y) * hh3);
            *reinterpret_cast<float2*>(out + (size_t)(row0 + rowA) * 128 + col) = oA;
            *reinterpret_cast<float2*>(out + (size_t)(row0 + rowB) * 128 + col) = oB;
        }
    }
}

// ================================================================================
// Launch
// ================================================================================
extern "C" void kernel_launch(void* const* d_in, const int* in_sizes, int n_in,
                              void* d_out, int out_size) {
    const float* atom_state = (const float*)d_in[0];
    const float* messages   = (const float*)d_in[1];
    const int*   conn       = (const int*)d_in[2];
    const float* kern       = (const float*)d_in[3];
    const float* rker       = (const float*)d_in[4];
    const float* bias       = (const float*)d_in[5];
    float* out = (float*)d_out;

    cudaFuncSetAttribute(gru_gemm_kernel, cudaFuncAttributeMaxDynamicSharedMemorySize, SMEM_TOTAL);

    prep_zero_kernel<<<384 + 2048, 256>>>(kern, rker);
    scatter_kernel<<<(NEDGE / 2 * 32) / 256, 256>>>(messages, conn);
    gru_gemm_kernel<<<ROWS_TOTAL / 64, 256, SMEM_TOTAL>>>(atom_state, bias, out);
}